// round 12
// baseline (speedup 1.0000x reference)
#include <cuda_runtime.h>
#include <math.h>

#define NN 100000
#define EE 1600000

typedef unsigned long long ull;

// fma.rn.f32x2: d.lo = a.lo*b.lo + d.lo ; d.hi = a.hi*b.hi + d.hi  (exact fp32 x2)
#define FMA_F32X2(d, a, b) \
    asm("fma.rn.f32x2 %0, %1, %2, %0;" : "+l"(d) : "l"(a), "l"(b))
#define UNPACK_F32X2(lo, hi, v) \
    asm("mov.b64 {%0, %1}, %2;" : "=f"(lo), "=f"(hi) : "l"(v))

__device__ __forceinline__ ull dupf(float x) {
    unsigned u = __float_as_uint(x);
    return (ull)u | ((ull)u << 32);
}

// ---------------- static device scratch (no allocation allowed) ----------------
__device__ float4   g_h4[NN * 16];    // per-layer transformed features (row stride C floats)
__device__ float4   g_a4[NN * 16];    // aggregation output (next layer input, pre-bias)
__device__ float4   g_als4[NN];       // attention logits (src side), one float4 = 4 heads
__device__ float4   g_ald4[NN];       // attention logits (dst side)
__device__ int      g_rowptr[NN + 1];
__device__ int      g_cursor[NN];
__device__ int      g_col[EE];
__device__ int      g_bsum[512];
__device__ unsigned g_gmax[16];       // per-layer (4) x per-head (4) global max of als, order-encoded
__device__ float    g_pool[64 * 8];
__device__ float    g_cnt[64];

// order-preserving float<->uint encoding (works across signs)
__device__ __forceinline__ unsigned f2u_ord(float x) {
    unsigned s = __float_as_uint(x);
    return (s & 0x80000000u) ? ~s : (s | 0x80000000u);
}
__device__ __forceinline__ float u2f_ord(unsigned u) {
    unsigned s = (u & 0x80000000u) ? (u ^ 0x80000000u) : ~u;
    return __uint_as_float(s);
}

// ---------------- CSR build ----------------
__global__ void k_zero_cursor() {
    int i = blockIdx.x * 256 + threadIdx.x;
    if (i < NN) g_cursor[i] = 0;
    int t = threadIdx.x;
    if (blockIdx.x == 0 && t < 16) g_gmax[t] = 0u;
    if (blockIdx.x == 1) {               // 256 threads: zero all 512 pool + 64 cnt
        g_pool[t] = 0.f;
        g_pool[t + 256] = 0.f;
        if (t < 64) g_cnt[t] = 0.f;
    }
}

__global__ void k_count(const int* __restrict__ ei) {
    int e = blockIdx.x * 256 + threadIdx.x;
    if (e < EE) atomicAdd(&g_cursor[ei[EE + e]], 1);
}

__global__ void k_scan1() {
    __shared__ int sm[256];
    int t = threadIdx.x;
    int i = blockIdx.x * 256 + t;
    int v = (i < NN) ? g_cursor[i] : 0;
    sm[t] = v;
    __syncthreads();
    for (int d = 1; d < 256; d <<= 1) {
        int x = (t >= d) ? sm[t - d] : 0;
        __syncthreads();
        sm[t] += x;
        __syncthreads();
    }
    if (i < NN) g_rowptr[i] = sm[t] - v;
    if (t == 255) g_bsum[blockIdx.x] = sm[255];
}

__global__ void k_scan2() {
    __shared__ int sm[512];
    int t = threadIdx.x;
    int v = (t < 391) ? g_bsum[t] : 0;
    sm[t] = v;
    __syncthreads();
    for (int d = 1; d < 512; d <<= 1) {
        int x = (t >= d) ? sm[t - d] : 0;
        __syncthreads();
        sm[t] += x;
        __syncthreads();
    }
    if (t < 391) g_bsum[t] = sm[t] - v;
    if (t == 511) g_rowptr[NN] = sm[511];
}

__global__ void k_scan3() {
    int i = blockIdx.x * 256 + threadIdx.x;
    if (i < NN) {
        g_rowptr[i] += g_bsum[blockIdx.x];
        g_cursor[i] = 0;
    }
}

__global__ void k_scatter(const int* __restrict__ ei) {
    int e = blockIdx.x * 256 + threadIdx.x;
    if (e < EE) {
        int d = ei[EE + e];
        int p = g_rowptr[d] + atomicAdd(&g_cursor[d], 1);
        g_col[p] = ei[e];
    }
}

// ---------------- register-blocked GEMM (f32x2 packed FMA) + attention-logit epilogue ----------------
// Block: 128 rows x C cols, 256 threads, BK=16. Thread tile TM x TN.
// Accumulators packed by row pairs; W staged duplicated ((w,w) ull) for FFMA2 broadcast.
template <int K, int C, bool RELU_IN, int LAYER>
__global__ __launch_bounds__(256) void k_gemm(const float* __restrict__ in_ext,
                                              const float* __restrict__ W,
                                              const float* __restrict__ asrc,
                                              const float* __restrict__ adst,
                                              const float* __restrict__ bin) {
    constexpr int OC = C / 4;                 // channels per head
    constexpr int TX = (C < 16) ? C : 16;     // threads along cols
    constexpr int TN = C / TX;                // cols per thread
    constexpr int TY = 256 / TX;              // threads along rows
    constexpr int TM = 128 / TY;              // rows per thread (8 or 4)
    constexpr int TM2 = TM / 2;
    constexpr int GSZ = OC / TN;              // lanes covering one head

    __shared__ float sIn[16][132];            // [k][row], rows 16B-aligned (132*4 = 33*16)
    __shared__ ull   sWd[16 * C];             // [k][col] duplicated (w,w)
    __shared__ float sB[K];
    __shared__ float sA[C];
    __shared__ float sD[C];
    __shared__ unsigned sMax[4];

    const float* in = RELU_IN ? (const float*)g_a4 : in_ext;
    int t = threadIdx.x;
    int tx = t % TX;
    int ty = t / TX;

    for (int i = t; i < C; i += 256) { sA[i] = asrc[i]; sD[i] = adst[i]; }
    if (RELU_IN) {
        for (int i = t; i < K; i += 256) sB[i] = bin[i];
    }
    if (t < 4) sMax[t] = 0u;
    __syncthreads();   // sB read by ALL threads in the staging loop below

    ull accp[TM2][TN];
#pragma unroll
    for (int p = 0; p < TM2; p++)
#pragma unroll
        for (int j = 0; j < TN; j++) accp[p][j] = 0ull;

    int rowbase = blockIdx.x * 128;

    for (int k0 = 0; k0 < K; k0 += 16) {
        // stage A tile (transpose to [k][row])
#pragma unroll
        for (int j = 0; j < 2; j++) {
            int i = t + j * 256;             // 0..511
            int q = i & 3;                   // k-subchunk (4 floats)
            int r = i >> 2;                  // row 0..127
            int gr = rowbase + r;
            float4 v = make_float4(0.f, 0.f, 0.f, 0.f);
            if (gr < NN) {
                v = *(const float4*)(in + gr * K + k0 + q * 4);
                if (RELU_IN) {
                    v.x = fmaxf(v.x + sB[k0 + q * 4 + 0], 0.f);
                    v.y = fmaxf(v.y + sB[k0 + q * 4 + 1], 0.f);
                    v.z = fmaxf(v.z + sB[k0 + q * 4 + 2], 0.f);
                    v.w = fmaxf(v.w + sB[k0 + q * 4 + 3], 0.f);
                }
            }
            sIn[q * 4 + 0][r] = v.x;
            sIn[q * 4 + 1][r] = v.y;
            sIn[q * 4 + 2][r] = v.z;
            sIn[q * 4 + 3][r] = v.w;
        }
        // stage W tile, duplicated for f32x2 broadcast
        if (t < 4 * C) {
            int kr = t / (C / 4);
            int cq = t % (C / 4);
            float4 w = *(const float4*)(W + (k0 + kr) * C + cq * 4);
            ull* dst = &sWd[kr * C + cq * 4];
            dst[0] = dupf(w.x);
            dst[1] = dupf(w.y);
            dst[2] = dupf(w.z);
            dst[3] = dupf(w.w);
        }
        __syncthreads();

#pragma unroll
        for (int kk = 0; kk < 16; kk++) {
            ull a2[TM2];
            const ull* arow = (const ull*)&sIn[kk][ty * TM];
#pragma unroll
            for (int p = 0; p < TM2; p++) a2[p] = arow[p];
            ull wb[TN];
            const ull* wrow = &sWd[kk * C + tx * TN];
#pragma unroll
            for (int j = 0; j < TN; j++) wb[j] = wrow[j];
#pragma unroll
            for (int p = 0; p < TM2; p++)
#pragma unroll
                for (int j = 0; j < TN; j++) FMA_F32X2(accp[p][j], a2[p], wb[j]);
        }
        __syncthreads();
    }

    // unpack accumulators
    float acc[TM][TN];
#pragma unroll
    for (int p = 0; p < TM2; p++)
#pragma unroll
        for (int j = 0; j < TN; j++) {
            float lo, hi;
            UNPACK_F32X2(lo, hi, accp[p][j]);
            acc[2 * p + 0][j] = lo;
            acc[2 * p + 1][j] = hi;
        }

    // epilogue: write h, per-head attention logits, global max of als
    int head = (tx * TN) / OC;
    float smax_local = -1e30f;
    float* galf = (float*)g_als4;
    float* gadf = (float*)g_ald4;
#pragma unroll
    for (int i = 0; i < TM; i++) {
        int gr = rowbase + ty * TM + i;
        bool vld = gr < NN;
        if (vld) {
            if (TN == 4) {
                float4 o = make_float4(acc[i][0], acc[i][1], acc[i][2], acc[i][3]);
                g_h4[gr * (C / 4) + tx] = o;
            } else if (TN == 2) {
                float2 o = make_float2(acc[i][0], acc[i][1]);
                ((float2*)g_h4)[gr * (C / 2) + tx] = o;
            } else {
                ((float*)g_h4)[gr * C + tx] = acc[i][0];
            }
        }
        float s = 0.f, d = 0.f;
#pragma unroll
        for (int j = 0; j < TN; j++) {
            s += acc[i][j] * sA[tx * TN + j];
            d += acc[i][j] * sD[tx * TN + j];
        }
#pragma unroll
        for (int dd = 1; dd < GSZ; dd <<= 1) {
            s += __shfl_xor_sync(0xffffffffu, s, dd);
            d += __shfl_xor_sync(0xffffffffu, d, dd);
        }
        if (vld && (tx % GSZ) == 0) {
            galf[gr * 4 + head] = s;
            gadf[gr * 4 + head] = d;
        }
        smax_local = fmaxf(smax_local, vld ? s : -1e30f);
    }
    if ((tx % GSZ) == 0) atomicMax(&sMax[head], f2u_ord(smax_local));
    __syncthreads();
    if (t < 4) atomicMax(&g_gmax[LAYER * 4 + t], sMax[t]);
}

// ---------------- attention aggregation ----------------
__device__ __forceinline__ float4 lrelu4(float4 v) {
    v.x = fmaxf(v.x, 0.2f * v.x);
    v.y = fmaxf(v.y, 0.2f * v.y);
    v.z = fmaxf(v.z, 0.2f * v.z);
    v.w = fmaxf(v.w, 0.2f * v.w);
    return v;
}
__device__ __forceinline__ float hsel(float4 v, int h) {
    return (h == 0) ? v.x : (h == 1) ? v.y : (h == 2) ? v.z : v.w;
}

// Warp per dst node. Edge-parallel exp into smem, then vectorized gather:
// each edge occupies L = C/VEC lanes; EPI = 32/L edges per iteration, batched 4x.
template <int C, int OC, int VEC, int LAYER>
__global__ __launch_bounds__(256) void k_agg() {
    constexpr int L = C / VEC;
    constexpr int EPI = 32 / L;
    __shared__ float4 sp4[8][32];   // exp(e-m) for 4 heads, per edge slot

    int warp = threadIdx.x >> 5;
    int lane = threadIdx.x & 31;
    int n = blockIdx.x * 8 + warp;
    if (n >= NN) return;

    int slot = lane / L;
    int lpos = lane % L;
    int ch0 = lpos * VEC;
    int head = ch0 / OC;

    const float* ghf = (const float*)g_h4;

    float4 ald4 = g_ald4[n];
    float4 asn  = g_als4[n];
    float4 es4;
    es4.x = asn.x + ald4.x; es4.y = asn.y + ald4.y;
    es4.z = asn.z + ald4.z; es4.w = asn.w + ald4.w;
    es4 = lrelu4(es4);

    float4 m4;
    m4.x = u2f_ord(g_gmax[LAYER * 4 + 0]) + ald4.x;
    m4.y = u2f_ord(g_gmax[LAYER * 4 + 1]) + ald4.y;
    m4.z = u2f_ord(g_gmax[LAYER * 4 + 2]) + ald4.z;
    m4.w = u2f_ord(g_gmax[LAYER * 4 + 3]) + ald4.w;
    m4 = lrelu4(m4);

    float4 ps4;
    ps4.x = __expf(es4.x - m4.x);
    ps4.y = __expf(es4.y - m4.y);
    ps4.z = __expf(es4.z - m4.z);
    ps4.w = __expf(es4.w - m4.w);
    float ps = hsel(ps4, head);

    // self-loop contribution (slot 0 only, to avoid duplication)
    float acc[VEC];
    float accs;
    {
        float hv[VEC];
        if (VEC == 4) {
            float4 h4 = *(const float4*)(ghf + n * C + ch0);
            hv[0] = h4.x; hv[1] = h4.y; hv[2] = h4.z; hv[3] = h4.w;
        } else {
            float2 h2 = *(const float2*)(ghf + n * C + ch0);
            hv[0] = h2.x; hv[1] = h2.y;
        }
        float psel = (slot == 0) ? ps : 0.f;
#pragma unroll
        for (int v = 0; v < VEC; v++) acc[v] = psel * hv[v];
        accs = psel;
    }

    int start = g_rowptr[n];
    int end = g_rowptr[n + 1];

    for (int j0 = start; j0 < end; j0 += 32) {
        int lj = j0 + lane;
        bool vld = lj < end;
        int src = vld ? g_col[lj] : 0;
        float4 a4 = g_als4[src];
        float4 e4;
        e4.x = a4.x + ald4.x; e4.y = a4.y + ald4.y;
        e4.z = a4.z + ald4.z; e4.w = a4.w + ald4.w;
        e4 = lrelu4(e4);
        float4 p4;
        p4.x = vld ? __expf(e4.x - m4.x) : 0.f;
        p4.y = vld ? __expf(e4.y - m4.y) : 0.f;
        p4.z = vld ? __expf(e4.z - m4.z) : 0.f;
        p4.w = vld ? __expf(e4.w - m4.w) : 0.f;
        sp4[warp][lane] = p4;
        __syncwarp();

        int cnt = min(32, end - j0);
        const float* pw = (const float*)&sp4[warp][0];
        // batches of 4 iterations (4*EPI edges), loads batched for MLP
        for (int jj = 0; jj < cnt; jj += 4 * EPI) {
            int e0 = jj + slot;
            int s0 = __shfl_sync(0xffffffffu, src, e0);
            int s1 = __shfl_sync(0xffffffffu, src, e0 + EPI);
            int s2 = __shfl_sync(0xffffffffu, src, e0 + 2 * EPI);
            int s3 = __shfl_sync(0xffffffffu, src, e0 + 3 * EPI);
            float p0 = pw[e0 * 4 + head];
            float p1 = pw[(e0 + EPI) * 4 + head];
            float p2 = pw[(e0 + 2 * EPI) * 4 + head];
            float p3 = pw[(e0 + 3 * EPI) * 4 + head];
            if (VEC == 4) {
                float4 h0 = *(const float4*)(ghf + s0 * C + ch0);
                float4 h1 = *(const float4*)(ghf + s1 * C + ch0);
                float4 h2 = *(const float4*)(ghf + s2 * C + ch0);
                float4 h3 = *(const float4*)(ghf + s3 * C + ch0);
                acc[0] += p0 * h0.x; acc[1] += p0 * h0.y; acc[2] += p0 * h0.z; acc[3] += p0 * h0.w;
                acc[0] += p1 * h1.x; acc[1] += p1 * h1.y; acc[2] += p1 * h1.z; acc[3] += p1 * h1.w;
                acc[0] += p2 * h2.x; acc[1] += p2 * h2.y; acc[2] += p2 * h2.z; acc[3] += p2 * h2.w;
                acc[0] += p3 * h3.x; acc[1] += p3 * h3.y; acc[2] += p3 * h3.z; acc[3] += p3 * h3.w;
            } else {
                float2 h0 = *(const float2*)(ghf + s0 * C + ch0);
                float2 h1 = *(const float2*)(ghf + s1 * C + ch0);
                float2 h2 = *(const float2*)(ghf + s2 * C + ch0);
                float2 h3 = *(const float2*)(ghf + s3 * C + ch0);
                acc[0] += p0 * h0.x; acc[1] += p0 * h0.y;
                acc[0] += p1 * h1.x; acc[1] += p1 * h1.y;
                acc[0] += p2 * h2.x; acc[1] += p2 * h2.y;
                acc[0] += p3 * h3.x; acc[1] += p3 * h3.y;
            }
            accs += p0 + p1 + p2 + p3;
        }
        __syncwarp();
    }

    // fold across edge slots (lanes with same channel group)
#pragma unroll
    for (int d = L; d < 32; d <<= 1) {
#pragma unroll
        for (int v = 0; v < VEC; v++) acc[v] += __shfl_xor_sync(0xffffffffu, acc[v], d);
        accs += __shfl_xor_sync(0xffffffffu, accs, d);
    }

    float inv = __fdividef(1.0f, accs + 1e-16f);
    if (slot == 0) {
        float* gaf = (float*)g_a4;
        if (VEC == 4) {
            float4 o = make_float4(acc[0] * inv, acc[1] * inv, acc[2] * inv, acc[3] * inv);
            *(float4*)(gaf + n * C + ch0) = o;
        } else {
            float2 o = make_float2(acc[0] * inv, acc[1] * inv);
            *(float2*)(gaf + n * C + ch0) = o;
        }
    }
}

// ---------------- pooling + FC ----------------
__global__ void k_pool(const int* __restrict__ batch, const float* __restrict__ b4) {
    int nn = blockIdx.x * 256 + threadIdx.x;
    if (nn >= NN) return;
    const float* ga = (const float*)g_a4;
    int b = batch[nn];
    atomicAdd(&g_cnt[b], 1.0f);
#pragma unroll
    for (int c = 0; c < 8; c++) {
        float v = fmaxf(ga[nn * 8 + c] + b4[c], 0.f);
        atomicAdd(&g_pool[b * 8 + c], v);
    }
}

__global__ void k_fc(const float* __restrict__ Wfc, const float* __restrict__ bfc,
                     float* __restrict__ out) {
    int id = blockIdx.x * 256 + threadIdx.x;
    if (id >= 64 * 32) return;
    int b = id >> 5;
    int o = id & 31;
    float invc = 1.0f / fmaxf(g_cnt[b], 1.0f);
    float acc = bfc[o];
#pragma unroll
    for (int c = 0; c < 8; c++) acc += (g_pool[b * 8 + c] * invc) * Wfc[c * 32 + o];
    out[id] = acc;
}

// ---------------- launch ----------------
extern "C" void kernel_launch(void* const* d_in, const int* in_sizes, int n_in,
                              void* d_out, int out_size) {
    const float* x     = (const float*)d_in[0];
    const int*   ei    = (const int*)d_in[1];
    const int*   batch = (const int*)d_in[2];
    const float* W1  = (const float*)d_in[3];
    const float* as1 = (const float*)d_in[4];
    const float* ad1 = (const float*)d_in[5];
    const float* b1  = (const float*)d_in[6];
    const float* W2  = (const float*)d_in[7];
    const float* as2 = (const float*)d_in[8];
    const float* ad2 = (const float*)d_in[9];
    const float* b2  = (const float*)d_in[10];
    const float* W3  = (const float*)d_in[11];
    const float* as3 = (const float*)d_in[12];
    const float* ad3 = (const float*)d_in[13];
    const float* b3  = (const float*)d_in[14];
    const float* W4  = (const float*)d_in[15];
    const float* as4 = (const float*)d_in[16];
    const float* ad4 = (const float*)d_in[17];
    const float* b4  = (const float*)d_in[18];
    const float* Wfc = (const float*)d_in[19];
    const float* bfc = (const float*)d_in[20];

    const int NBLK = (NN + 255) / 256;   // 391
    const int EBLK = (EE + 255) / 256;   // 6250
    const int GBLK = (NN + 127) / 128;   // 782
    const int ABLK = (NN + 7) / 8;       // 12500

    // CSR build; gemm1 kept at 4th launch (the slot ncu captures) for A/B.
    k_zero_cursor<<<NBLK, 256>>>();
    k_count<<<EBLK, 256>>>(ei);
    k_scan1<<<NBLK, 256>>>();
    k_gemm<128, 64, false, 0><<<GBLK, 256>>>(x, W1, as1, ad1, nullptr);
    k_scan2<<<1, 512>>>();
    k_scan3<<<NBLK, 256>>>();
    k_scatter<<<EBLK, 256>>>(ei);

    // layer 1: 128 -> 4x16
    k_agg<64, 16, 4, 0><<<ABLK, 256>>>();
    // layer 2: 64 -> 4x8
    k_gemm<64, 32, true, 1><<<GBLK, 256>>>(nullptr, W2, as2, ad2, b1);
    k_agg<32, 8, 4, 1><<<ABLK, 256>>>();
    // layer 3: 32 -> 4x4
    k_gemm<32, 16, true, 2><<<GBLK, 256>>>(nullptr, W3, as3, ad3, b2);
    k_agg<16, 4, 4, 2><<<ABLK, 256>>>();
    // layer 4: 16 -> 4x2
    k_gemm<16, 8, true, 3><<<GBLK, 256>>>(nullptr, W4, as4, ad4, b3);
    k_agg<8, 2, 2, 3><<<ABLK, 256>>>();

    // global mean pool + FC (pool/cnt zeroed in k_zero_cursor block 1)
    k_pool<<<NBLK, 256>>>(batch, b4);
    k_fc<<<8, 256>>>(Wfc, bfc, (float*)d_out);
}

// round 14
// speedup vs baseline: 1.0846x; 1.0846x over previous
#include <cuda_runtime.h>
#include <math.h>

#define NN 100000
#define EE 1600000

typedef unsigned long long ull;

// fma.rn.f32x2: d.lo = a.lo*b.lo + d.lo ; d.hi = a.hi*b.hi + d.hi  (exact fp32 x2)
#define FMA_F32X2(d, a, b) \
    asm("fma.rn.f32x2 %0, %1, %2, %0;" : "+l"(d) : "l"(a), "l"(b))
#define UNPACK_F32X2(lo, hi, v) \
    asm("mov.b64 {%0, %1}, %2;" : "=f"(lo), "=f"(hi) : "l"(v))
#define DUPF(d, s) \
    asm("mov.b64 %0, {%1, %1};" : "=l"(d) : "f"(s))

// ---------------- static device scratch (no allocation allowed) ----------------
__device__ float4   g_h4[NN * 16];    // per-layer transformed features (row stride C floats)
__device__ float4   g_a4[NN * 16];    // aggregation output (next layer input, pre-bias)
__device__ float4   g_als4[NN];       // attention logits (src side), one float4 = 4 heads
__device__ float4   g_ald4[NN];       // attention logits (dst side)
__device__ int      g_rowptr[NN + 1];
__device__ int      g_cursor[NN];
__device__ int      g_col[EE];
__device__ int      g_bsum[512];
__device__ unsigned g_gmax[16];       // per-layer (4) x per-head (4) global max of als, order-encoded
__device__ float    g_pool[64 * 8];
__device__ float    g_cnt[64];

// order-preserving float<->uint encoding (works across signs)
__device__ __forceinline__ unsigned f2u_ord(float x) {
    unsigned s = __float_as_uint(x);
    return (s & 0x80000000u) ? ~s : (s | 0x80000000u);
}
__device__ __forceinline__ float u2f_ord(unsigned u) {
    unsigned s = (u & 0x80000000u) ? (u ^ 0x80000000u) : ~u;
    return __uint_as_float(s);
}

// ---------------- CSR build ----------------
__global__ void k_zero_cursor() {
    int i = blockIdx.x * 256 + threadIdx.x;
    if (i < NN) g_cursor[i] = 0;
    int t = threadIdx.x;
    if (blockIdx.x == 0 && t < 16) g_gmax[t] = 0u;
    if (blockIdx.x == 1) {               // 256 threads: zero all 512 pool + 64 cnt
        g_pool[t] = 0.f;
        g_pool[t + 256] = 0.f;
        if (t < 64) g_cnt[t] = 0.f;
    }
}

__global__ void k_count(const int* __restrict__ ei) {
    int e = blockIdx.x * 256 + threadIdx.x;
    if (e < EE) atomicAdd(&g_cursor[ei[EE + e]], 1);
}

__global__ void k_scan1() {
    __shared__ int sm[256];
    int t = threadIdx.x;
    int i = blockIdx.x * 256 + t;
    int v = (i < NN) ? g_cursor[i] : 0;
    sm[t] = v;
    __syncthreads();
    for (int d = 1; d < 256; d <<= 1) {
        int x = (t >= d) ? sm[t - d] : 0;
        __syncthreads();
        sm[t] += x;
        __syncthreads();
    }
    if (i < NN) g_rowptr[i] = sm[t] - v;
    if (t == 255) g_bsum[blockIdx.x] = sm[255];
}

__global__ void k_scan2() {
    __shared__ int sm[512];
    int t = threadIdx.x;
    int v = (t < 391) ? g_bsum[t] : 0;
    sm[t] = v;
    __syncthreads();
    for (int d = 1; d < 512; d <<= 1) {
        int x = (t >= d) ? sm[t - d] : 0;
        __syncthreads();
        sm[t] += x;
        __syncthreads();
    }
    if (t < 391) g_bsum[t] = sm[t] - v;
    if (t == 511) g_rowptr[NN] = sm[511];
}

__global__ void k_scan3() {
    int i = blockIdx.x * 256 + threadIdx.x;
    if (i < NN) {
        g_rowptr[i] += g_bsum[blockIdx.x];
        g_cursor[i] = 0;
    }
}

__global__ void k_scatter(const int* __restrict__ ei) {
    int e = blockIdx.x * 256 + threadIdx.x;
    if (e < EE) {
        int d = ei[EE + e];
        int p = g_rowptr[d] + atomicAdd(&g_cursor[d], 1);
        g_col[p] = ei[e];
    }
}

// ---------------- register-blocked GEMM (FFMA2, zero extra smem traffic) ----------------
// Block: 128 rows x C cols, 256 threads, BK=16. Thread tile TM x TN.
// TN>=2: column-paired accumulators; W pairs read as ull from plain-float sW,
//        A broadcast duplicated in registers (MOV, alu pipe).
// TN==1: row-paired accumulators; A pairs read as ull from sIn, w duplicated in regs.
template <int K, int C, bool RELU_IN, int LAYER>
__global__ __launch_bounds__(256) void k_gemm(const float* __restrict__ in_ext,
                                              const float* __restrict__ W,
                                              const float* __restrict__ asrc,
                                              const float* __restrict__ adst,
                                              const float* __restrict__ bin) {
    constexpr int OC = C / 4;                 // channels per head
    constexpr int TX = (C < 16) ? C : 16;     // threads along cols
    constexpr int TN = C / TX;                // cols per thread
    constexpr int TY = 256 / TX;              // threads along rows
    constexpr int TM = 128 / TY;              // rows per thread (8 or 4)
    constexpr int GSZ = OC / TN;              // lanes covering one head
    constexpr bool CP = (TN >= 2);            // column-pair mode
    constexpr int PA = CP ? TM : TM / 2;      // accumulator rows
    constexpr int PB = CP ? TN / 2 : 1;       // accumulator col-pairs

    __shared__ float sIn[16][132];            // [k][row], rows 16B-aligned (132*4 = 33*16)
    __shared__ float4 sW4[16 * (C / 4)];      // [k][col/4], plain floats (same as R10)
    __shared__ float sB[K];
    __shared__ float sA[C];
    __shared__ float sD[C];
    __shared__ unsigned sMax[4];
    const float* sW = (const float*)sW4;

    const float* in = RELU_IN ? (const float*)g_a4 : in_ext;
    int t = threadIdx.x;
    int tx = t % TX;
    int ty = t / TX;

    for (int i = t; i < C; i += 256) { sA[i] = asrc[i]; sD[i] = adst[i]; }
    if (RELU_IN) {
        for (int i = t; i < K; i += 256) sB[i] = bin[i];
    }
    if (t < 4) sMax[t] = 0u;
    __syncthreads();   // sB read by ALL threads in the staging loop below

    ull accp[PA][PB];
#pragma unroll
    for (int p = 0; p < PA; p++)
#pragma unroll
        for (int j = 0; j < PB; j++) accp[p][j] = 0ull;

    int rowbase = blockIdx.x * 128;

    for (int k0 = 0; k0 < K; k0 += 16) {
        // stage A tile (transpose to [k][row])
#pragma unroll
        for (int j = 0; j < 2; j++) {
            int i = t + j * 256;             // 0..511
            int q = i & 3;                   // k-subchunk (4 floats)
            int r = i >> 2;                  // row 0..127
            int gr = rowbase + r;
            float4 v = make_float4(0.f, 0.f, 0.f, 0.f);
            if (gr < NN) {
                v = *(const float4*)(in + gr * K + k0 + q * 4);
                if (RELU_IN) {
                    v.x = fmaxf(v.x + sB[k0 + q * 4 + 0], 0.f);
                    v.y = fmaxf(v.y + sB[k0 + q * 4 + 1], 0.f);
                    v.z = fmaxf(v.z + sB[k0 + q * 4 + 2], 0.f);
                    v.w = fmaxf(v.w + sB[k0 + q * 4 + 3], 0.f);
                }
            }
            sIn[q * 4 + 0][r] = v.x;
            sIn[q * 4 + 1][r] = v.y;
            sIn[q * 4 + 2][r] = v.z;
            sIn[q * 4 + 3][r] = v.w;
        }
        // stage W tile (plain floats)
        if (t < 4 * C) {
            int kr = t / (C / 4);
            int cq = t % (C / 4);
            sW4[kr * (C / 4) + cq] = *(const float4*)(W + (k0 + kr) * C + cq * 4);
        }
        __syncthreads();

#pragma unroll
        for (int kk = 0; kk < 16; kk++) {
            if (CP) {
                // column-pair: A broadcast dup in regs, W pairs straight from smem
                float a[TM];
                {
                    float4 a0 = *(const float4*)&sIn[kk][ty * TM];
                    a[0] = a0.x; a[1] = a0.y; a[2] = a0.z; a[3] = a0.w;
                    if (TM == 8) {
                        float4 a1 = *(const float4*)&sIn[kk][ty * TM + 4];
                        a[4] = a1.x; a[5] = a1.y; a[6] = a1.z; a[7] = a1.w;
                    }
                }
                ull a2[TM];
#pragma unroll
                for (int p = 0; p < TM; p++) DUPF(a2[p], a[p]);
                ull wb[PB];
                const ull* wrow = (const ull*)&sW[kk * C + tx * TN];
#pragma unroll
                for (int j = 0; j < PB; j++) wb[j] = wrow[j];
#pragma unroll
                for (int p = 0; p < PA; p++)
#pragma unroll
                    for (int j = 0; j < PB; j++) FMA_F32X2(accp[p][j], a2[p], wb[j]);
            } else {
                // row-pair: A pairs straight from smem, scalar w dup in regs
                ull a2[PA];
                const ull* arow = (const ull*)&sIn[kk][ty * TM];
#pragma unroll
                for (int p = 0; p < PA; p++) a2[p] = arow[p];
                float w = sW[kk * C + tx];
                ull wd;
                DUPF(wd, w);
#pragma unroll
                for (int p = 0; p < PA; p++) FMA_F32X2(accp[p][0], a2[p], wd);
            }
        }
        __syncthreads();
    }

    // unpack accumulators
    float acc[TM][TN];
    if (CP) {
#pragma unroll
        for (int p = 0; p < PA; p++)
#pragma unroll
            for (int j = 0; j < PB; j++) {
                float lo, hi;
                UNPACK_F32X2(lo, hi, accp[p][j]);
                acc[p][2 * j + 0] = lo;
                acc[p][2 * j + 1] = hi;
            }
    } else {
#pragma unroll
        for (int p = 0; p < PA; p++) {
            float lo, hi;
            UNPACK_F32X2(lo, hi, accp[p][0]);
            acc[2 * p + 0][0] = lo;
            acc[2 * p + 1][0] = hi;
        }
    }

    // epilogue: write h, per-head attention logits, global max of als
    int head = (tx * TN) / OC;
    float smax_local = -1e30f;
    float* galf = (float*)g_als4;
    float* gadf = (float*)g_ald4;
#pragma unroll
    for (int i = 0; i < TM; i++) {
        int gr = rowbase + ty * TM + i;
        bool vld = gr < NN;
        if (vld) {
            if (TN == 4) {
                float4 o = make_float4(acc[i][0], acc[i][1], acc[i][2], acc[i][3]);
                g_h4[gr * (C / 4) + tx] = o;
            } else if (TN == 2) {
                float2 o = make_float2(acc[i][0], acc[i][1]);
                ((float2*)g_h4)[gr * (C / 2) + tx] = o;
            } else {
                ((float*)g_h4)[gr * C + tx] = acc[i][0];
            }
        }
        float s = 0.f, d = 0.f;
#pragma unroll
        for (int j = 0; j < TN; j++) {
            s += acc[i][j] * sA[tx * TN + j];
            d += acc[i][j] * sD[tx * TN + j];
        }
#pragma unroll
        for (int dd = 1; dd < GSZ; dd <<= 1) {
            s += __shfl_xor_sync(0xffffffffu, s, dd);
            d += __shfl_xor_sync(0xffffffffu, d, dd);
        }
        if (vld && (tx % GSZ) == 0) {
            galf[gr * 4 + head] = s;
            gadf[gr * 4 + head] = d;
        }
        smax_local = fmaxf(smax_local, vld ? s : -1e30f);
    }
    if ((tx % GSZ) == 0) atomicMax(&sMax[head], f2u_ord(smax_local));
    __syncthreads();
    if (t < 4) atomicMax(&g_gmax[LAYER * 4 + t], sMax[t]);
}

// ---------------- attention aggregation ----------------
__device__ __forceinline__ float4 lrelu4(float4 v) {
    v.x = fmaxf(v.x, 0.2f * v.x);
    v.y = fmaxf(v.y, 0.2f * v.y);
    v.z = fmaxf(v.z, 0.2f * v.z);
    v.w = fmaxf(v.w, 0.2f * v.w);
    return v;
}
__device__ __forceinline__ float hsel(float4 v, int h) {
    return (h == 0) ? v.x : (h == 1) ? v.y : (h == 2) ? v.z : v.w;
}

// Warp per dst node. Edge-parallel exp into smem, then vectorized gather:
// each edge occupies L = C/VEC lanes; EPI = 32/L edges per iteration, batched 4x.
template <int C, int OC, int VEC, int LAYER>
__global__ __launch_bounds__(256) void k_agg() {
    constexpr int L = C / VEC;
    constexpr int EPI = 32 / L;
    __shared__ float4 sp4[8][32];   // exp(e-m) for 4 heads, per edge slot

    int warp = threadIdx.x >> 5;
    int lane = threadIdx.x & 31;
    int n = blockIdx.x * 8 + warp;
    if (n >= NN) return;

    int slot = lane / L;
    int lpos = lane % L;
    int ch0 = lpos * VEC;
    int head = ch0 / OC;

    const float* ghf = (const float*)g_h4;

    float4 ald4 = g_ald4[n];
    float4 asn  = g_als4[n];
    float4 es4;
    es4.x = asn.x + ald4.x; es4.y = asn.y + ald4.y;
    es4.z = asn.z + ald4.z; es4.w = asn.w + ald4.w;
    es4 = lrelu4(es4);

    float4 m4;
    m4.x = u2f_ord(g_gmax[LAYER * 4 + 0]) + ald4.x;
    m4.y = u2f_ord(g_gmax[LAYER * 4 + 1]) + ald4.y;
    m4.z = u2f_ord(g_gmax[LAYER * 4 + 2]) + ald4.z;
    m4.w = u2f_ord(g_gmax[LAYER * 4 + 3]) + ald4.w;
    m4 = lrelu4(m4);

    float4 ps4;
    ps4.x = __expf(es4.x - m4.x);
    ps4.y = __expf(es4.y - m4.y);
    ps4.z = __expf(es4.z - m4.z);
    ps4.w = __expf(es4.w - m4.w);
    float ps = hsel(ps4, head);

    // self-loop contribution (slot 0 only, to avoid duplication)
    float acc[VEC];
    float accs;
    {
        float hv[VEC];
        if (VEC == 4) {
            float4 h4 = *(const float4*)(ghf + n * C + ch0);
            hv[0] = h4.x; hv[1] = h4.y; hv[2] = h4.z; hv[3] = h4.w;
        } else {
            float2 h2 = *(const float2*)(ghf + n * C + ch0);
            hv[0] = h2.x; hv[1] = h2.y;
        }
        float psel = (slot == 0) ? ps : 0.f;
#pragma unroll
        for (int v = 0; v < VEC; v++) acc[v] = psel * hv[v];
        accs = psel;
    }

    int start = g_rowptr[n];
    int end = g_rowptr[n + 1];

    for (int j0 = start; j0 < end; j0 += 32) {
        int lj = j0 + lane;
        bool vld = lj < end;
        int src = vld ? g_col[lj] : 0;
        float4 a4 = g_als4[src];
        float4 e4;
        e4.x = a4.x + ald4.x; e4.y = a4.y + ald4.y;
        e4.z = a4.z + ald4.z; e4.w = a4.w + ald4.w;
        e4 = lrelu4(e4);
        float4 p4;
        p4.x = vld ? __expf(e4.x - m4.x) : 0.f;
        p4.y = vld ? __expf(e4.y - m4.y) : 0.f;
        p4.z = vld ? __expf(e4.z - m4.z) : 0.f;
        p4.w = vld ? __expf(e4.w - m4.w) : 0.f;
        sp4[warp][lane] = p4;
        __syncwarp();

        int cnt = min(32, end - j0);
        const float* pw = (const float*)&sp4[warp][0];
        // batches of 4 iterations (4*EPI edges), loads batched for MLP
        for (int jj = 0; jj < cnt; jj += 4 * EPI) {
            int e0 = jj + slot;
            int s0 = __shfl_sync(0xffffffffu, src, e0);
            int s1 = __shfl_sync(0xffffffffu, src, e0 + EPI);
            int s2 = __shfl_sync(0xffffffffu, src, e0 + 2 * EPI);
            int s3 = __shfl_sync(0xffffffffu, src, e0 + 3 * EPI);
            float p0 = pw[e0 * 4 + head];
            float p1 = pw[(e0 + EPI) * 4 + head];
            float p2 = pw[(e0 + 2 * EPI) * 4 + head];
            float p3 = pw[(e0 + 3 * EPI) * 4 + head];
            if (VEC == 4) {
                float4 h0 = *(const float4*)(ghf + s0 * C + ch0);
                float4 h1 = *(const float4*)(ghf + s1 * C + ch0);
                float4 h2 = *(const float4*)(ghf + s2 * C + ch0);
                float4 h3 = *(const float4*)(ghf + s3 * C + ch0);
                acc[0] += p0 * h0.x; acc[1] += p0 * h0.y; acc[2] += p0 * h0.z; acc[3] += p0 * h0.w;
                acc[0] += p1 * h1.x; acc[1] += p1 * h1.y; acc[2] += p1 * h1.z; acc[3] += p1 * h1.w;
                acc[0] += p2 * h2.x; acc[1] += p2 * h2.y; acc[2] += p2 * h2.z; acc[3] += p2 * h2.w;
                acc[0] += p3 * h3.x; acc[1] += p3 * h3.y; acc[2] += p3 * h3.z; acc[3] += p3 * h3.w;
            } else {
                float2 h0 = *(const float2*)(ghf + s0 * C + ch0);
                float2 h1 = *(const float2*)(ghf + s1 * C + ch0);
                float2 h2 = *(const float2*)(ghf + s2 * C + ch0);
                float2 h3 = *(const float2*)(ghf + s3 * C + ch0);
                acc[0] += p0 * h0.x; acc[1] += p0 * h0.y;
                acc[0] += p1 * h1.x; acc[1] += p1 * h1.y;
                acc[0] += p2 * h2.x; acc[1] += p2 * h2.y;
                acc[0] += p3 * h3.x; acc[1] += p3 * h3.y;
            }
            accs += p0 + p1 + p2 + p3;
        }
        __syncwarp();
    }

    // fold across edge slots (lanes with same channel group)
#pragma unroll
    for (int d = L; d < 32; d <<= 1) {
#pragma unroll
        for (int v = 0; v < VEC; v++) acc[v] += __shfl_xor_sync(0xffffffffu, acc[v], d);
        accs += __shfl_xor_sync(0xffffffffu, accs, d);
    }

    float inv = __fdividef(1.0f, accs + 1e-16f);
    if (slot == 0) {
        float* gaf = (float*)g_a4;
        if (VEC == 4) {
            float4 o = make_float4(acc[0] * inv, acc[1] * inv, acc[2] * inv, acc[3] * inv);
            *(float4*)(gaf + n * C + ch0) = o;
        } else {
            float2 o = make_float2(acc[0] * inv, acc[1] * inv);
            *(float2*)(gaf + n * C + ch0) = o;
        }
    }
}

// ---------------- pooling + FC ----------------
__global__ void k_pool(const int* __restrict__ batch, const float* __restrict__ b4) {
    int nn = blockIdx.x * 256 + threadIdx.x;
    if (nn >= NN) return;
    const float* ga = (const float*)g_a4;
    int b = batch[nn];
    atomicAdd(&g_cnt[b], 1.0f);
#pragma unroll
    for (int c = 0; c < 8; c++) {
        float v = fmaxf(ga[nn * 8 + c] + b4[c], 0.f);
        atomicAdd(&g_pool[b * 8 + c], v);
    }
}

__global__ void k_fc(const float* __restrict__ Wfc, const float* __restrict__ bfc,
                     float* __restrict__ out) {
    int id = blockIdx.x * 256 + threadIdx.x;
    if (id >= 64 * 32) return;
    int b = id >> 5;
    int o = id & 31;
    float invc = 1.0f / fmaxf(g_cnt[b], 1.0f);
    float acc = bfc[o];
#pragma unroll
    for (int c = 0; c < 8; c++) acc += (g_pool[b * 8 + c] * invc) * Wfc[c * 32 + o];
    out[id] = acc;
}

// ---------------- launch ----------------
extern "C" void kernel_launch(void* const* d_in, const int* in_sizes, int n_in,
                              void* d_out, int out_size) {
    const float* x     = (const float*)d_in[0];
    const int*   ei    = (const int*)d_in[1];
    const int*   batch = (const int*)d_in[2];
    const float* W1  = (const float*)d_in[3];
    const float* as1 = (const float*)d_in[4];
    const float* ad1 = (const float*)d_in[5];
    const float* b1  = (const float*)d_in[6];
    const float* W2  = (const float*)d_in[7];
    const float* as2 = (const float*)d_in[8];
    const float* ad2 = (const float*)d_in[9];
    const float* b2  = (const float*)d_in[10];
    const float* W3  = (const float*)d_in[11];
    const float* as3 = (const float*)d_in[12];
    const float* ad3 = (const float*)d_in[13];
    const float* b3  = (const float*)d_in[14];
    const float* W4  = (const float*)d_in[15];
    const float* as4 = (const float*)d_in[16];
    const float* ad4 = (const float*)d_in[17];
    const float* b4  = (const float*)d_in[18];
    const float* Wfc = (const float*)d_in[19];
    const float* bfc = (const float*)d_in[20];

    const int NBLK = (NN + 255) / 256;   // 391
    const int EBLK = (EE + 255) / 256;   // 6250
    const int GBLK = (NN + 127) / 128;   // 782
    const int ABLK = (NN + 7) / 8;       // 12500

    // CSR build; gemm1 kept at 4th launch (the slot ncu captures) for A/B.
    k_zero_cursor<<<NBLK, 256>>>();
    k_count<<<EBLK, 256>>>(ei);
    k_scan1<<<NBLK, 256>>>();
    k_gemm<128, 64, false, 0><<<GBLK, 256>>>(x, W1, as1, ad1, nullptr);
    k_scan2<<<1, 512>>>();
    k_scan3<<<NBLK, 256>>>();
    k_scatter<<<EBLK, 256>>>(ei);

    // layer 1: 128 -> 4x16
    k_agg<64, 16, 4, 0><<<ABLK, 256>>>();
    // layer 2: 64 -> 4x8
    k_gemm<64, 32, true, 1><<<GBLK, 256>>>(nullptr, W2, as2, ad2, b1);
    k_agg<32, 8, 4, 1><<<ABLK, 256>>>();
    // layer 3: 32 -> 4x4
    k_gemm<32, 16, true, 2><<<GBLK, 256>>>(nullptr, W3, as3, ad3, b2);
    k_agg<16, 4, 4, 2><<<ABLK, 256>>>();
    // layer 4: 16 -> 4x2
    k_gemm<16, 8, true, 3><<<GBLK, 256>>>(nullptr, W4, as4, ad4, b3);
    k_agg<8, 2, 2, 3><<<ABLK, 256>>>();

    // global mean pool + FC (pool/cnt zeroed in k_zero_cursor block 1)
    k_pool<<<NBLK, 256>>>(batch, b4);
    k_fc<<<8, 256>>>(Wfc, bfc, (float*)d_out);
}

// round 15
// speedup vs baseline: 1.5502x; 1.4293x over previous
#include <cuda_runtime.h>
#include <math.h>

#define NN 100000
#define EE 1600000

typedef unsigned long long ull;

// fma.rn.f32x2: d.lo = a.lo*b.lo + d.lo ; d.hi = a.hi*b.hi + d.hi  (exact fp32 x2)
#define FMA_F32X2(d, a, b) \
    asm("fma.rn.f32x2 %0, %1, %2, %0;" : "+l"(d) : "l"(a), "l"(b))
#define UNPACK_F32X2(lo, hi, v) \
    asm("mov.b64 {%0, %1}, %2;" : "=f"(lo), "=f"(hi) : "l"(v))
#define DUPF(d, s) \
    asm("mov.b64 %0, {%1, %1};" : "=l"(d) : "f"(s))

// ---------------- static device scratch (no allocation allowed) ----------------
__device__ float4   g_h4[NN * 16];    // per-layer transformed features (row stride C floats)
__device__ float4   g_a4[NN * 16];    // aggregation output (next layer input, pre-bias)
__device__ float4   g_als4[NN];       // attention logits (src side), one float4 = 4 heads
__device__ float4   g_ald4[NN];       // attention logits (dst side)
__device__ int      g_rowptr[NN + 1];
__device__ int      g_cursor[NN];
__device__ int      g_col[EE];
__device__ int      g_bsum[512];
__device__ unsigned g_gmax[16];       // per-layer (4) x per-head (4) global max of als, order-encoded
__device__ float    g_pool[64 * 8];
__device__ float    g_cnt[64];

// order-preserving float<->uint encoding (works across signs)
__device__ __forceinline__ unsigned f2u_ord(float x) {
    unsigned s = __float_as_uint(x);
    return (s & 0x80000000u) ? ~s : (s | 0x80000000u);
}
__device__ __forceinline__ float u2f_ord(unsigned u) {
    unsigned s = (u & 0x80000000u) ? (u ^ 0x80000000u) : ~u;
    return __uint_as_float(s);
}

// ---------------- CSR build ----------------
__global__ void k_zero_cursor() {
    int i = blockIdx.x * 256 + threadIdx.x;
    if (i < NN) g_cursor[i] = 0;
    int t = threadIdx.x;
    if (blockIdx.x == 0 && t < 16) g_gmax[t] = 0u;
    if (blockIdx.x == 1) {               // 256 threads: zero all 512 pool + 64 cnt
        g_pool[t] = 0.f;
        g_pool[t + 256] = 0.f;
        if (t < 64) g_cnt[t] = 0.f;
    }
}

__global__ void k_count(const int* __restrict__ ei) {
    int e = blockIdx.x * 256 + threadIdx.x;
    if (e < EE) atomicAdd(&g_cursor[ei[EE + e]], 1);
}

__global__ void k_scan1() {
    __shared__ int sm[256];
    int t = threadIdx.x;
    int i = blockIdx.x * 256 + t;
    int v = (i < NN) ? g_cursor[i] : 0;
    sm[t] = v;
    __syncthreads();
    for (int d = 1; d < 256; d <<= 1) {
        int x = (t >= d) ? sm[t - d] : 0;
        __syncthreads();
        sm[t] += x;
        __syncthreads();
    }
    if (i < NN) g_rowptr[i] = sm[t] - v;
    if (t == 255) g_bsum[blockIdx.x] = sm[255];
}

__global__ void k_scan2() {
    __shared__ int sm[512];
    int t = threadIdx.x;
    int v = (t < 391) ? g_bsum[t] : 0;
    sm[t] = v;
    __syncthreads();
    for (int d = 1; d < 512; d <<= 1) {
        int x = (t >= d) ? sm[t - d] : 0;
        __syncthreads();
        sm[t] += x;
        __syncthreads();
    }
    if (t < 391) g_bsum[t] = sm[t] - v;
    if (t == 511) g_rowptr[NN] = sm[511];
}

__global__ void k_scan3() {
    int i = blockIdx.x * 256 + threadIdx.x;
    if (i < NN) {
        g_rowptr[i] += g_bsum[blockIdx.x];
        g_cursor[i] = 0;
    }
}

__global__ void k_scatter(const int* __restrict__ ei) {
    int e = blockIdx.x * 256 + threadIdx.x;
    if (e < EE) {
        int d = ei[EE + e];
        int p = g_rowptr[d] + atomicAdd(&g_cursor[d], 1);
        g_col[p] = ei[e];
    }
}

// ---------------- register-blocked GEMM (FFMA2, zero extra smem traffic) ----------------
template <int K, int C, bool RELU_IN, int LAYER>
__global__ __launch_bounds__(256) void k_gemm(const float* __restrict__ in_ext,
                                              const float* __restrict__ W,
                                              const float* __restrict__ asrc,
                                              const float* __restrict__ adst,
                                              const float* __restrict__ bin) {
    constexpr int OC = C / 4;
    constexpr int TX = (C < 16) ? C : 16;
    constexpr int TN = C / TX;
    constexpr int TY = 256 / TX;
    constexpr int TM = 128 / TY;
    constexpr int GSZ = OC / TN;
    constexpr bool CP = (TN >= 2);
    constexpr int PA = CP ? TM : TM / 2;
    constexpr int PB = CP ? TN / 2 : 1;

    __shared__ float sIn[16][132];
    __shared__ float4 sW4[16 * (C / 4)];
    __shared__ float sB[K];
    __shared__ float sA[C];
    __shared__ float sD[C];
    __shared__ unsigned sMax[4];
    const float* sW = (const float*)sW4;

    const float* in = RELU_IN ? (const float*)g_a4 : in_ext;
    int t = threadIdx.x;
    int tx = t % TX;
    int ty = t / TX;

    for (int i = t; i < C; i += 256) { sA[i] = asrc[i]; sD[i] = adst[i]; }
    if (RELU_IN) {
        for (int i = t; i < K; i += 256) sB[i] = bin[i];
    }
    if (t < 4) sMax[t] = 0u;
    __syncthreads();   // sB read by ALL threads in the staging loop below

    ull accp[PA][PB];
#pragma unroll
    for (int p = 0; p < PA; p++)
#pragma unroll
        for (int j = 0; j < PB; j++) accp[p][j] = 0ull;

    int rowbase = blockIdx.x * 128;

    for (int k0 = 0; k0 < K; k0 += 16) {
#pragma unroll
        for (int j = 0; j < 2; j++) {
            int i = t + j * 256;
            int q = i & 3;
            int r = i >> 2;
            int gr = rowbase + r;
            float4 v = make_float4(0.f, 0.f, 0.f, 0.f);
            if (gr < NN) {
                v = *(const float4*)(in + gr * K + k0 + q * 4);
                if (RELU_IN) {
                    v.x = fmaxf(v.x + sB[k0 + q * 4 + 0], 0.f);
                    v.y = fmaxf(v.y + sB[k0 + q * 4 + 1], 0.f);
                    v.z = fmaxf(v.z + sB[k0 + q * 4 + 2], 0.f);
                    v.w = fmaxf(v.w + sB[k0 + q * 4 + 3], 0.f);
                }
            }
            sIn[q * 4 + 0][r] = v.x;
            sIn[q * 4 + 1][r] = v.y;
            sIn[q * 4 + 2][r] = v.z;
            sIn[q * 4 + 3][r] = v.w;
        }
        if (t < 4 * C) {
            int kr = t / (C / 4);
            int cq = t % (C / 4);
            sW4[kr * (C / 4) + cq] = *(const float4*)(W + (k0 + kr) * C + cq * 4);
        }
        __syncthreads();

#pragma unroll
        for (int kk = 0; kk < 16; kk++) {
            if (CP) {
                float a[TM];
                {
                    float4 a0 = *(const float4*)&sIn[kk][ty * TM];
                    a[0] = a0.x; a[1] = a0.y; a[2] = a0.z; a[3] = a0.w;
                    if (TM == 8) {
                        float4 a1 = *(const float4*)&sIn[kk][ty * TM + 4];
                        a[4] = a1.x; a[5] = a1.y; a[6] = a1.z; a[7] = a1.w;
                    }
                }
                ull a2[TM];
#pragma unroll
                for (int p = 0; p < TM; p++) DUPF(a2[p], a[p]);
                ull wb[PB];
                const ull* wrow = (const ull*)&sW[kk * C + tx * TN];
#pragma unroll
                for (int j = 0; j < PB; j++) wb[j] = wrow[j];
#pragma unroll
                for (int p = 0; p < PA; p++)
#pragma unroll
                    for (int j = 0; j < PB; j++) FMA_F32X2(accp[p][j], a2[p], wb[j]);
            } else {
                ull a2[PA];
                const ull* arow = (const ull*)&sIn[kk][ty * TM];
#pragma unroll
                for (int p = 0; p < PA; p++) a2[p] = arow[p];
                float w = sW[kk * C + tx];
                ull wd;
                DUPF(wd, w);
#pragma unroll
                for (int p = 0; p < PA; p++) FMA_F32X2(accp[p][0], a2[p], wd);
            }
        }
        __syncthreads();
    }

    float acc[TM][TN];
    if (CP) {
#pragma unroll
        for (int p = 0; p < PA; p++)
#pragma unroll
            for (int j = 0; j < PB; j++) {
                float lo, hi;
                UNPACK_F32X2(lo, hi, accp[p][j]);
                acc[p][2 * j + 0] = lo;
                acc[p][2 * j + 1] = hi;
            }
    } else {
#pragma unroll
        for (int p = 0; p < PA; p++) {
            float lo, hi;
            UNPACK_F32X2(lo, hi, accp[p][0]);
            acc[2 * p + 0][0] = lo;
            acc[2 * p + 1][0] = hi;
        }
    }

    int head = (tx * TN) / OC;
    float smax_local = -1e30f;
    float* galf = (float*)g_als4;
    float* gadf = (float*)g_ald4;
#pragma unroll
    for (int i = 0; i < TM; i++) {
        int gr = rowbase + ty * TM + i;
        bool vld = gr < NN;
        if (vld) {
            if (TN == 4) {
                float4 o = make_float4(acc[i][0], acc[i][1], acc[i][2], acc[i][3]);
                g_h4[gr * (C / 4) + tx] = o;
            } else if (TN == 2) {
                float2 o = make_float2(acc[i][0], acc[i][1]);
                ((float2*)g_h4)[gr * (C / 2) + tx] = o;
            } else {
                ((float*)g_h4)[gr * C + tx] = acc[i][0];
            }
        }
        float s = 0.f, d = 0.f;
#pragma unroll
        for (int j = 0; j < TN; j++) {
            s += acc[i][j] * sA[tx * TN + j];
            d += acc[i][j] * sD[tx * TN + j];
        }
#pragma unroll
        for (int dd = 1; dd < GSZ; dd <<= 1) {
            s += __shfl_xor_sync(0xffffffffu, s, dd);
            d += __shfl_xor_sync(0xffffffffu, d, dd);
        }
        if (vld && (tx % GSZ) == 0) {
            galf[gr * 4 + head] = s;
            gadf[gr * 4 + head] = d;
        }
        smax_local = fmaxf(smax_local, vld ? s : -1e30f);
    }
    if ((tx % GSZ) == 0) atomicMax(&sMax[head], f2u_ord(smax_local));
    __syncthreads();
    if (t < 4) atomicMax(&g_gmax[LAYER * 4 + t], sMax[t]);
}

// ---------------- attention aggregation: subgroup-per-node ----------------
__device__ __forceinline__ float4 lrelu4(float4 v) {
    v.x = fmaxf(v.x, 0.2f * v.x);
    v.y = fmaxf(v.y, 0.2f * v.y);
    v.z = fmaxf(v.z, 0.2f * v.z);
    v.w = fmaxf(v.w, 0.2f * v.w);
    return v;
}
__device__ __forceinline__ float hsel(float4 v, int h) {
    return (h == 0) ? v.x : (h == 1) ? v.y : (h == 2) ? v.z : v.w;
}

// Warp = G subgroups of S = C/VEC lanes; each subgroup owns one node.
// Every lane walks ALL the node's edges (VEC channels each), so the per-lane
// softmax denominator is complete -- no cross-lane fold. Requires VEC <= OC
// (a lane never spans heads). Uniform trip count via warp-max degree.
template <int C, int OC, int VEC, int LAYER>
__global__ __launch_bounds__(256) void k_agg() {
    constexpr int S = C / VEC;       // lanes per node
    constexpr int G = 32 / S;        // nodes per warp
    __shared__ float4 sp4[8][32];    // per-lane exp(e-m) float4 (4 heads)

    int warp = threadIdx.x >> 5;
    int lane = threadIdx.x & 31;
    int g = lane / S;
    int lpos = lane % S;
    int ch0 = lpos * VEC;
    int head = ch0 / OC;

    int n = (blockIdx.x * 8 + warp) * G + g;
    bool nvalid = n < NN;
    int nsafe = nvalid ? n : 0;

    const float* ghf = (const float*)g_h4;

    float4 ald4 = g_ald4[nsafe];
    float4 asn  = g_als4[nsafe];
    float4 es4;
    es4.x = asn.x + ald4.x; es4.y = asn.y + ald4.y;
    es4.z = asn.z + ald4.z; es4.w = asn.w + ald4.w;
    es4 = lrelu4(es4);

    float4 m4;
    m4.x = u2f_ord(g_gmax[LAYER * 4 + 0]) + ald4.x;
    m4.y = u2f_ord(g_gmax[LAYER * 4 + 1]) + ald4.y;
    m4.z = u2f_ord(g_gmax[LAYER * 4 + 2]) + ald4.z;
    m4.w = u2f_ord(g_gmax[LAYER * 4 + 3]) + ald4.w;
    m4 = lrelu4(m4);

    float4 ps4;
    ps4.x = __expf(es4.x - m4.x);
    ps4.y = __expf(es4.y - m4.y);
    ps4.z = __expf(es4.z - m4.z);
    ps4.w = __expf(es4.w - m4.w);
    float ps = hsel(ps4, head);

    int start = 0, end = 0;
    if (nvalid) {
        start = g_rowptr[n];
        end = g_rowptr[n + 1];
    }
    int mdeg = end - start;
#pragma unroll
    for (int d = 16; d; d >>= 1) mdeg = max(mdeg, __shfl_xor_sync(0xffffffffu, mdeg, d));

    // self-loop: every lane covers distinct channels; accs is per-lane (per-head)
    float acc0 = 0.f, acc1 = 0.f, acc2 = 0.f, acc3 = 0.f, accs = 0.f;
    if (nvalid) {
        if (VEC == 4) {
            float4 hv = *(const float4*)(ghf + n * C + ch0);
            acc0 = ps * hv.x; acc1 = ps * hv.y; acc2 = ps * hv.z; acc3 = ps * hv.w;
        } else {
            float2 hv = *(const float2*)(ghf + n * C + ch0);
            acc0 = ps * hv.x; acc1 = ps * hv.y;
        }
        accs = ps;
    }

    for (int it = 0; it < mdeg; it += S) {
        int lj = start + it + lpos;
        bool vld = lj < end;
        int src = vld ? g_col[lj] : nsafe;
        float4 a4 = g_als4[src];
        float4 e4;
        e4.x = a4.x + ald4.x; e4.y = a4.y + ald4.y;
        e4.z = a4.z + ald4.z; e4.w = a4.w + ald4.w;
        e4 = lrelu4(e4);
        float4 p4;
        p4.x = vld ? __expf(e4.x - m4.x) : 0.f;
        p4.y = vld ? __expf(e4.y - m4.y) : 0.f;
        p4.z = vld ? __expf(e4.z - m4.z) : 0.f;
        p4.w = vld ? __expf(e4.w - m4.w) : 0.f;
        sp4[warp][lane] = p4;
        __syncwarp();

        const float* pw = (const float*)&sp4[warp][0];
        int base = g * S;
#pragma unroll
        for (int j = 0; j < S; j += 4) {   // S >= 4 always
            int ss[4];
            float pp[4];
#pragma unroll
            for (int q = 0; q < 4; q++) {
                ss[q] = __shfl_sync(0xffffffffu, src, base + j + q);
                pp[q] = pw[(base + j + q) * 4 + head];
            }
            if (VEC == 4) {
                float4 hh[4];
#pragma unroll
                for (int q = 0; q < 4; q++) hh[q] = *(const float4*)(ghf + ss[q] * C + ch0);
#pragma unroll
                for (int q = 0; q < 4; q++) {
                    acc0 += pp[q] * hh[q].x; acc1 += pp[q] * hh[q].y;
                    acc2 += pp[q] * hh[q].z; acc3 += pp[q] * hh[q].w;
                }
            } else {
                float2 hh[4];
#pragma unroll
                for (int q = 0; q < 4; q++) hh[q] = *(const float2*)(ghf + ss[q] * C + ch0);
#pragma unroll
                for (int q = 0; q < 4; q++) {
                    acc0 += pp[q] * hh[q].x; acc1 += pp[q] * hh[q].y;
                }
            }
            accs += pp[0] + pp[1] + pp[2] + pp[3];
        }
        __syncwarp();
    }

    if (nvalid) {
        float inv = __fdividef(1.0f, accs + 1e-16f);
        float* gaf = (float*)g_a4;
        if (VEC == 4) {
            float4 o = make_float4(acc0 * inv, acc1 * inv, acc2 * inv, acc3 * inv);
            *(float4*)(gaf + n * C + ch0) = o;
        } else {
            float2 o = make_float2(acc0 * inv, acc1 * inv);
            *(float2*)(gaf + n * C + ch0) = o;
        }
    }
}

// ---------------- pooling + FC ----------------
__global__ void k_pool(const int* __restrict__ batch, const float* __restrict__ b4) {
    int nn = blockIdx.x * 256 + threadIdx.x;
    if (nn >= NN) return;
    const float* ga = (const float*)g_a4;
    int b = batch[nn];
    atomicAdd(&g_cnt[b], 1.0f);
#pragma unroll
    for (int c = 0; c < 8; c++) {
        float v = fmaxf(ga[nn * 8 + c] + b4[c], 0.f);
        atomicAdd(&g_pool[b * 8 + c], v);
    }
}

__global__ void k_fc(const float* __restrict__ Wfc, const float* __restrict__ bfc,
                     float* __restrict__ out) {
    int id = blockIdx.x * 256 + threadIdx.x;
    if (id >= 64 * 32) return;
    int b = id >> 5;
    int o = id & 31;
    float invc = 1.0f / fmaxf(g_cnt[b], 1.0f);
    float acc = bfc[o];
#pragma unroll
    for (int c = 0; c < 8; c++) acc += (g_pool[b * 8 + c] * invc) * Wfc[c * 32 + o];
    out[id] = acc;
}

// ---------------- launch ----------------
extern "C" void kernel_launch(void* const* d_in, const int* in_sizes, int n_in,
                              void* d_out, int out_size) {
    const float* x     = (const float*)d_in[0];
    const int*   ei    = (const int*)d_in[1];
    const int*   batch = (const int*)d_in[2];
    const float* W1  = (const float*)d_in[3];
    const float* as1 = (const float*)d_in[4];
    const float* ad1 = (const float*)d_in[5];
    const float* b1  = (const float*)d_in[6];
    const float* W2  = (const float*)d_in[7];
    const float* as2 = (const float*)d_in[8];
    const float* ad2 = (const float*)d_in[9];
    const float* b2  = (const float*)d_in[10];
    const float* W3  = (const float*)d_in[11];
    const float* as3 = (const float*)d_in[12];
    const float* ad3 = (const float*)d_in[13];
    const float* b3  = (const float*)d_in[14];
    const float* W4  = (const float*)d_in[15];
    const float* as4 = (const float*)d_in[16];
    const float* ad4 = (const float*)d_in[17];
    const float* b4  = (const float*)d_in[18];
    const float* Wfc = (const float*)d_in[19];
    const float* bfc = (const float*)d_in[20];

    const int NBLK = (NN + 255) / 256;   // 391
    const int EBLK = (EE + 255) / 256;   // 6250
    const int GBLK = (NN + 127) / 128;   // 782

    // CSR build; gemm1 kept at 4th launch (the slot ncu captures) for A/B.
    k_zero_cursor<<<NBLK, 256>>>();
    k_count<<<EBLK, 256>>>(ei);
    k_scan1<<<NBLK, 256>>>();
    k_gemm<128, 64, false, 0><<<GBLK, 256>>>(x, W1, as1, ad1, nullptr);
    k_scan2<<<1, 512>>>();
    k_scan3<<<NBLK, 256>>>();
    k_scatter<<<EBLK, 256>>>(ei);

    // layer 1: 128 -> 4x16   (S=16, G=2 nodes/warp)
    k_agg<64, 16, 4, 0><<<(NN + 15) / 16, 256>>>();
    // layer 2: 64 -> 4x8     (S=8, G=4)
    k_gemm<64, 32, true, 1><<<GBLK, 256>>>(nullptr, W2, as2, ad2, b1);
    k_agg<32, 8, 4, 1><<<(NN + 31) / 32, 256>>>();
    // layer 3: 32 -> 4x4     (S=4, G=8)
    k_gemm<32, 16, true, 2><<<GBLK, 256>>>(nullptr, W3, as3, ad3, b2);
    k_agg<16, 4, 4, 2><<<(NN + 63) / 64, 256>>>();
    // layer 4: 16 -> 4x2     (VEC=2, S=4, G=8)
    k_gemm<16, 8, true, 3><<<GBLK, 256>>>(nullptr, W4, as4, ad4, b3);
    k_agg<8, 2, 2, 3><<<(NN + 63) / 64, 256>>>();

    // global mean pool + FC (pool/cnt zeroed in k_zero_cursor block 1)
    k_pool<<<NBLK, 256>>>(batch, b4);
    k_fc<<<8, 256>>>(Wfc, bfc, (float*)d_out);
}